// round 5
// baseline (speedup 1.0000x reference)
#include <cuda_runtime.h>
#include <cuda_bf16.h>
#include <math.h>
#include <stdint.h>

#define DIM       128
#define SNEG      256
#define STRIDE    136          // padded bf16 row stride (conflict-free fragment LDS)
#define MTILE     128          // rows per tile
#define INV_T     10.0f
#define LOG_S     5.545177444479562f   // log(256)
#define GRIDP     296          // persistent CTAs (2 per SM)
#define MAXBLOCKS 4096

__device__ float g_partial[MAXBLOCKS];
__device__ int   g_idx_is64;

// ---------------------------------------------------------------------------
// Kernel 0: detect index dtype (int32 vs int64) from first 1KB of negatives.
// ---------------------------------------------------------------------------
__global__ void detect_idx_kernel(const void* __restrict__ neg, int n) {
    const long long* p = (const long long*)neg;
    long long v = p[threadIdx.x];              // 128 threads -> 1KB
    int ok = (v >= 0 && v < (long long)n);
    int all = __syncthreads_and(ok);
    if (threadIdx.x == 0) g_idx_is64 = all;
}

__device__ __forceinline__ long long load_index(const void* p, long long i, int is64) {
    return is64 ? ((const long long*)p)[i] : (long long)((const int*)p)[i];
}

__device__ __forceinline__ float bdot(unsigned a, float2 fb) {
    float2 fa = __bfloat1622float2(*reinterpret_cast<__nv_bfloat162*>(&a));
    return fa.x * fb.x + fa.y * fb.y;
}

// ---------------------------------------------------------------------------
// Main persistent kernel: fused normalize + positive dots + bf16 mma.sync GEMM
// vs 256 negatives + logsumexp. 256 threads, 2 CTAs/SM.
//   smem: sB (256x128 bf16, stride 136) staged+normalized ONCE per CTA,
//         sA (128x128 bf16, stride 136) per tile, sPos, sRed.
// ---------------------------------------------------------------------------
__global__ __launch_bounds__(256, 2) void main_kernel(
    const float* __restrict__ E,
    const void*  __restrict__ pos_idx,
    const void*  __restrict__ neg_idx,
    int n, int ntiles)
{
    extern __shared__ char smem_raw[];
    __nv_bfloat16* sB = reinterpret_cast<__nv_bfloat16*>(smem_raw);
    __nv_bfloat16* sA = sB + SNEG * STRIDE;
    float* sPos = reinterpret_cast<float*>(sA + MTILE * STRIDE);
    float* sRed = sPos + MTILE;

    const int tid  = threadIdx.x;
    const int lane = tid & 31;
    const int warp = tid >> 5;
    const int is64 = g_idx_is64;

    // ---- stage + normalize all 256 negatives ONCE (1 thread/row, 2-pass) ----
    {
        long long vr = load_index(neg_idx, tid, is64);
        const float4* src = reinterpret_cast<const float4*>(E + (size_t)vr * DIM);
        float s0 = 0.f, s1 = 0.f, s2 = 0.f, s3 = 0.f;
#pragma unroll
        for (int j = 0; j < 32; j += 4) {
            float4 a = src[j], b = src[j + 1], c = src[j + 2], d = src[j + 3];
            s0 += a.x * a.x + a.y * a.y + a.z * a.z + a.w * a.w;
            s1 += b.x * b.x + b.y * b.y + b.z * b.z + b.w * b.w;
            s2 += c.x * c.x + c.y * c.y + c.z * c.z + c.w * c.w;
            s3 += d.x * d.x + d.y * d.y + d.z * d.z + d.w * d.w;
        }
        float inv = 1.0f / fmaxf(sqrtf((s0 + s1) + (s2 + s3)), 1e-12f);
        __nv_bfloat16* dst = sB + tid * STRIDE;
#pragma unroll
        for (int j = 0; j < 32; j++) {
            float4 v = src[j];                       // L1 hit (re-read)
            __nv_bfloat162 p0 = __floats2bfloat162_rn(v.x * inv, v.y * inv);
            __nv_bfloat162 p1 = __floats2bfloat162_rn(v.z * inv, v.w * inv);
            uint2 st;
            st.x = reinterpret_cast<unsigned&>(p0);
            st.y = reinterpret_cast<unsigned&>(p1);
            *reinterpret_cast<uint2*>(dst + j * 4) = st;
        }
    }

    float local = 0.0f;
    const int r  = tid >> 1;          // row within tile (2 threads per row)
    const int h  = tid & 1;           // half selector
    const int g  = lane >> 2;         // 0..7
    const int t4 = lane & 3;          // 0..3
    const int rbase = warp * 16;

    for (int tile = blockIdx.x; tile < ntiles; tile += GRIDP) {
        const long long tile0 = (long long)tile * MTILE;
        __syncthreads();              // previous tile's GEMM reads done

        // ---- stage + normalize Q tile: 2 threads/row, 64 floats each ----
        {
            long long gr = tile0 + r;
            __nv_bfloat16* dst = sA + r * STRIDE + h * 64;
            if (gr < n) {
                const float4* src = reinterpret_cast<const float4*>(
                    E + (size_t)gr * DIM + h * 64);
                float s0 = 0.f, s1 = 0.f;
#pragma unroll
                for (int j = 0; j < 16; j += 2) {
                    float4 a = src[j], b = src[j + 1];
                    s0 += a.x * a.x + a.y * a.y + a.z * a.z + a.w * a.w;
                    s1 += b.x * b.x + b.y * b.y + b.z * b.z + b.w * b.w;
                }
                float ss = s0 + s1;
                ss += __shfl_xor_sync(0xffffffffu, ss, 1);   // partner half
                float inv = 1.0f / fmaxf(sqrtf(ss), 1e-12f);
#pragma unroll
                for (int j = 0; j < 16; j++) {
                    float4 v = src[j];                       // L1 hit
                    __nv_bfloat162 p0 = __floats2bfloat162_rn(v.x * inv, v.y * inv);
                    __nv_bfloat162 p1 = __floats2bfloat162_rn(v.z * inv, v.w * inv);
                    uint2 st;
                    st.x = reinterpret_cast<unsigned&>(p0);
                    st.y = reinterpret_cast<unsigned&>(p1);
                    *reinterpret_cast<uint2*>(dst + j * 4) = st;
                }
            } else {
                float dummy = 0.f;
                __shfl_xor_sync(0xffffffffu, dummy, 1);      // keep shfl uniform
                uint2 z = make_uint2(0u, 0u);
#pragma unroll
                for (int j = 0; j < 16; j++)
                    *reinterpret_cast<uint2*>(dst + j * 4) = z;
            }
        }
        __syncthreads();

        // ---- positive logits: 2 threads/row, gather fp32 row, dot vs sA ----
        {
            long long gr = tile0 + r;
            float dot = 0.0f, ssb = 0.0f;
            if (gr < n) {
                long long p = load_index(pos_idx, gr, is64);
                const float4* pb = reinterpret_cast<const float4*>(
                    E + (size_t)p * DIM + h * 64);
                const uint2* qa = reinterpret_cast<const uint2*>(
                    sA + r * STRIDE + h * 64);
#pragma unroll
                for (int j = 0; j < 16; j++) {
                    float4 b = pb[j];
                    uint2  a = qa[j];
                    ssb += b.x * b.x + b.y * b.y + b.z * b.z + b.w * b.w;
                    dot += bdot(a.x, make_float2(b.x, b.y))
                         + bdot(a.y, make_float2(b.z, b.w));
                }
            }
            dot += __shfl_xor_sync(0xffffffffu, dot, 1);
            ssb += __shfl_xor_sync(0xffffffffu, ssb, 1);
            if (h == 0)
                sPos[r] = dot * (1.0f / fmaxf(sqrtf(ssb), 1e-12f)) * INV_T;
        }
        __syncthreads();

        // ---- GEMM: warp = 16 rows x 256 negs, 4 chunks of 64 ----
        const __nv_bfloat16* qlo = sA + (rbase + g) * STRIDE + 2 * t4;
        const __nv_bfloat16* qhi = sA + (rbase + g + 8) * STRIDE + 2 * t4;
        const __nv_bfloat16* vb  = sB + g * STRIDE + 2 * t4;

        float rs_lo = 0.0f, rs_hi = 0.0f;
#pragma unroll
        for (int c = 0; c < 4; c++) {
            float acc[8][4];
#pragma unroll
            for (int i = 0; i < 8; i++) {
                acc[i][0] = 0.f; acc[i][1] = 0.f;
                acc[i][2] = 0.f; acc[i][3] = 0.f;
            }
#pragma unroll
            for (int k0 = 0; k0 < 8; k0++) {
                int k = k0 * 16;
                unsigned a0 = *reinterpret_cast<const unsigned*>(qlo + k);
                unsigned a1 = *reinterpret_cast<const unsigned*>(qhi + k);
                unsigned a2 = *reinterpret_cast<const unsigned*>(qlo + k + 8);
                unsigned a3 = *reinterpret_cast<const unsigned*>(qhi + k + 8);
#pragma unroll
                for (int nt = 0; nt < 8; nt++) {
                    const __nv_bfloat16* vp = vb + (c * 64 + nt * 8) * STRIDE + k;
                    unsigned b0 = *reinterpret_cast<const unsigned*>(vp);
                    unsigned b1 = *reinterpret_cast<const unsigned*>(vp + 8);
                    asm volatile(
                        "mma.sync.aligned.m16n8k16.row.col.f32.bf16.bf16.f32 "
                        "{%0,%1,%2,%3}, {%4,%5,%6,%7}, {%8,%9}, {%0,%1,%2,%3};\n"
                        : "+f"(acc[nt][0]), "+f"(acc[nt][1]),
                          "+f"(acc[nt][2]), "+f"(acc[nt][3])
                        : "r"(a0), "r"(a1), "r"(a2), "r"(a3),
                          "r"(b0), "r"(b1));
                }
            }
#pragma unroll
            for (int nt = 0; nt < 8; nt++) {
                rs_lo += __expf(acc[nt][0] * INV_T) + __expf(acc[nt][1] * INV_T);
                rs_hi += __expf(acc[nt][2] * INV_T) + __expf(acc[nt][3] * INV_T);
            }
        }

        rs_lo += __shfl_xor_sync(0xffffffffu, rs_lo, 1);
        rs_lo += __shfl_xor_sync(0xffffffffu, rs_lo, 2);
        rs_hi += __shfl_xor_sync(0xffffffffu, rs_hi, 1);
        rs_hi += __shfl_xor_sync(0xffffffffu, rs_hi, 2);

        if (t4 == 0) {
            long long g0 = tile0 + rbase + g;
            if (g0 < n)     local += sPos[rbase + g]     - (logf(rs_lo) - LOG_S);
            if (g0 + 8 < n) local += sPos[rbase + g + 8] - (logf(rs_hi) - LOG_S);
        }
    }

    // ---- block reduction of per-thread sums (deterministic) ----
#pragma unroll
    for (int o = 16; o > 0; o >>= 1)
        local += __shfl_xor_sync(0xffffffffu, local, o);
    __syncthreads();
    if (lane == 0) sRed[warp] = local;
    __syncthreads();
    if (tid == 0) {
        float s = 0.0f;
#pragma unroll
        for (int w = 0; w < 8; w++) s += sRed[w];
        g_partial[blockIdx.x] = s;
    }
}

// ---------------------------------------------------------------------------
// Final deterministic reduction, loss = -sum / N
// ---------------------------------------------------------------------------
__global__ void finalize_kernel(float* __restrict__ out, int n, int nblocks) {
    __shared__ float sh[256];
    float s = 0.0f;
    for (int i = threadIdx.x; i < nblocks; i += 256) s += g_partial[i];
    sh[threadIdx.x] = s;
    __syncthreads();
    for (int o = 128; o > 0; o >>= 1) {
        if (threadIdx.x < o) sh[threadIdx.x] += sh[threadIdx.x + o];
        __syncthreads();
    }
    if (threadIdx.x == 0) out[0] = -sh[0] / (float)n;
}

// ---------------------------------------------------------------------------
extern "C" void kernel_launch(void* const* d_in, const int* in_sizes, int n_in,
                              void* d_out, int out_size) {
    const float* E   = (const float*)d_in[0];
    const void*  pos = d_in[1];
    const void*  neg = d_in[2];
    int n = in_sizes[1];   // number of edges

    detect_idx_kernel<<<1, 128>>>(neg, n);

    int ntiles = (n + MTILE - 1) / MTILE;
    size_t smem = (size_t)(SNEG * STRIDE + MTILE * STRIDE) * sizeof(__nv_bfloat16)
                + (size_t)(MTILE + 8) * sizeof(float);
    cudaFuncSetAttribute(main_kernel,
                         cudaFuncAttributeMaxDynamicSharedMemorySize, (int)smem);
    main_kernel<<<GRIDP, 256, smem>>>(E, pos, neg, n, ntiles);

    finalize_kernel<<<1, 256>>>((float*)d_out, n, GRIDP);
}